// round 12
// baseline (speedup 1.0000x reference)
#include <cuda_runtime.h>

// inputs [B=8, T=4096, C=1024] fp32 -> out[b,t,c] = mean over s<=t of in[b,s,c]
//
// Three-kernel partitioned scan, tuned for L2 reuse:
//  K1 seg_sum : per-(b,seg) segment sums (reads input once, fills L2)
//  K2 seg_scan: exclusive scan of the 64 segment sums per column (2 MB, ~2us)
//  K3 scan_out: re-reads input in REVERSE segment order (MRU-first -> L2 hits
//               on the input K1 just streamed), adds carry, scales by rcp(t+1),
//               writes output with __stcs streaming stores (don't evict input).
// All traffic float4. 1024 CTAs x 128 threads for K1/K3.

#define B_DIM   8
#define T_DIM   4096
#define C_DIM   1024
#define CQ      (C_DIM / 4)           // 256 float4 per row
#define CT      128                   // threads per CTA (owns 128 float4 = 512 cols)
#define CTILES  2
#define SEGLEN  64
#define NSEG    (T_DIM / SEGLEN)      // 64

// 8 * 64 * 256 float4 = 2 MB scratch; __device__ global (no allocations).
__device__ float4 g_partials[B_DIM * NSEG * CQ];

__device__ __forceinline__ void f4add(float4& a, const float4 b) {
    a.x += b.x; a.y += b.y; a.z += b.z; a.w += b.w;
}

__global__ __launch_bounds__(CT) void seg_sum_kernel(const float* __restrict__ in) {
    const int seg = blockIdx.x;
    const int b   = blockIdx.z;
    const int cq  = blockIdx.y * CT + threadIdx.x;

    const float4* p = reinterpret_cast<const float4*>(
        in + ((size_t)b * T_DIM + (size_t)seg * SEGLEN) * C_DIM) + cq;

    float4 s0 = make_float4(0.f, 0.f, 0.f, 0.f);
    float4 s1 = make_float4(0.f, 0.f, 0.f, 0.f);
#pragma unroll 8
    for (int t = 0; t < SEGLEN; t += 2) {
        f4add(s0, p[(size_t)t * CQ]);
        f4add(s1, p[(size_t)(t + 1) * CQ]);
    }
    f4add(s0, s1);
    g_partials[(b * NSEG + seg) * CQ + cq] = s0;
}

// Exclusive scan over the 64 segments, per (b, cq) column. 2048 threads total.
// Batched prefetch of 8 keeps the serial chain short (~8 L2 round-trips).
__global__ __launch_bounds__(256) void seg_scan_kernel() {
    const int idx = blockIdx.x * blockDim.x + threadIdx.x;   // 0 .. B*CQ-1
    if (idx >= B_DIM * CQ) return;
    const int b  = idx / CQ;
    const int cq = idx % CQ;

    float4 run = make_float4(0.f, 0.f, 0.f, 0.f);
    for (int s0 = 0; s0 < NSEG; s0 += 8) {
        float4 v[8];
#pragma unroll
        for (int j = 0; j < 8; ++j)
            v[j] = g_partials[(b * NSEG + s0 + j) * CQ + cq];
#pragma unroll
        for (int j = 0; j < 8; ++j) {
            const float4 t = v[j];
            g_partials[(b * NSEG + s0 + j) * CQ + cq] = run;
            f4add(run, t);
        }
    }
}

__global__ __launch_bounds__(CT) void scan_out_kernel(const float* __restrict__ in,
                                                      float* __restrict__ out) {
    // Reverse segment order: re-read the input MRU-first relative to K1's
    // streaming fill of L2 (LRU cyclic-reuse fix).
    const int seg = (NSEG - 1) - blockIdx.x;
    const int b   = blockIdx.z;
    const int cq  = blockIdx.y * CT + threadIdx.x;
    const int t0  = seg * SEGLEN;

    __shared__ float s_rcp[SEGLEN];
    if (threadIdx.x < SEGLEN)
        s_rcp[threadIdx.x] = __frcp_rn((float)(t0 + threadIdx.x + 1));
    __syncthreads();

    float4 carry = g_partials[(b * NSEG + seg) * CQ + cq];   // exclusive prefix

    const float4* pin = reinterpret_cast<const float4*>(
        in + ((size_t)b * T_DIM + t0) * C_DIM) + cq;
    float4* pout = reinterpret_cast<float4*>(
        out + ((size_t)b * T_DIM + t0) * C_DIM) + cq;

#pragma unroll 8
    for (int t = 0; t < SEGLEN; ++t) {
        f4add(carry, pin[(size_t)t * CQ]);
        const float r = s_rcp[t];
        float4 o;
        o.x = carry.x * r; o.y = carry.y * r; o.z = carry.z * r; o.w = carry.w * r;
        __stcs(pout + (size_t)t * CQ, o);   // streaming store: don't pollute L2
    }
}

extern "C" void kernel_launch(void* const* d_in, const int* in_sizes, int n_in,
                              void* d_out, int out_size) {
    (void)in_sizes; (void)n_in; (void)out_size;
    const float* in = (const float*)d_in[0];
    float* out = (float*)d_out;

    dim3 grid(NSEG, CTILES, B_DIM);          // 64 x 2 x 8 = 1024 CTAs
    seg_sum_kernel<<<grid, CT>>>(in);
    seg_scan_kernel<<<(B_DIM * CQ + 255) / 256, 256>>>();
    scan_out_kernel<<<grid, CT>>>(in, out);
}